// round 3
// baseline (speedup 1.0000x reference)
#include <cuda_runtime.h>
#include <math.h>

namespace {

constexpr int V  = 3;
constexpr int C  = 32;
constexpr int CD = 8;
constexpr int D  = 32;
constexpr int H  = 128;
constexpr int W  = 160;
constexpr int HW = H * W;
constexpr int KD = 4;            // depths per thread in cost kernel
constexpr float LAMB = 1.5f;

// Cost volume scratch (D, H, W)
__device__ float g_cost[D * HW];

// ---------------------------------------------------------------------------
// fp32 closed-form 4x4 inverse (adjugate).
// ---------------------------------------------------------------------------
__device__ __forceinline__ void inv4x4(const float* m, float* inv) {
    inv[0]  =  m[5]*m[10]*m[15] - m[5]*m[11]*m[14] - m[9]*m[6]*m[15]
             + m[9]*m[7]*m[14] + m[13]*m[6]*m[11] - m[13]*m[7]*m[10];
    inv[4]  = -m[4]*m[10]*m[15] + m[4]*m[11]*m[14] + m[8]*m[6]*m[15]
             - m[8]*m[7]*m[14] - m[12]*m[6]*m[11] + m[12]*m[7]*m[10];
    inv[8]  =  m[4]*m[9]*m[15] - m[4]*m[11]*m[13] - m[8]*m[5]*m[15]
             + m[8]*m[7]*m[13] + m[12]*m[5]*m[11] - m[12]*m[7]*m[9];
    inv[12] = -m[4]*m[9]*m[14] + m[4]*m[10]*m[13] + m[8]*m[5]*m[14]
             - m[8]*m[6]*m[13] - m[12]*m[5]*m[10] + m[12]*m[6]*m[9];
    inv[1]  = -m[1]*m[10]*m[15] + m[1]*m[11]*m[14] + m[9]*m[2]*m[15]
             - m[9]*m[3]*m[14] - m[13]*m[2]*m[11] + m[13]*m[3]*m[10];
    inv[5]  =  m[0]*m[10]*m[15] - m[0]*m[11]*m[14] - m[8]*m[2]*m[15]
             + m[8]*m[3]*m[14] + m[12]*m[2]*m[11] - m[12]*m[3]*m[10];
    inv[9]  = -m[0]*m[9]*m[15] + m[0]*m[11]*m[13] + m[8]*m[1]*m[15]
             - m[8]*m[3]*m[13] - m[12]*m[1]*m[11] + m[12]*m[3]*m[9];
    inv[13] =  m[0]*m[9]*m[14] - m[0]*m[10]*m[13] - m[8]*m[1]*m[14]
             + m[8]*m[2]*m[13] + m[12]*m[1]*m[10] - m[12]*m[2]*m[9];
    inv[2]  =  m[1]*m[6]*m[15] - m[1]*m[7]*m[14] - m[5]*m[2]*m[15]
             + m[5]*m[3]*m[14] + m[13]*m[2]*m[7] - m[13]*m[3]*m[6];
    inv[6]  = -m[0]*m[6]*m[15] + m[0]*m[7]*m[14] + m[4]*m[2]*m[15]
             - m[4]*m[3]*m[14] - m[12]*m[2]*m[7] + m[12]*m[3]*m[6];
    inv[10] =  m[0]*m[5]*m[15] - m[0]*m[7]*m[13] - m[4]*m[1]*m[15]
             + m[4]*m[3]*m[13] + m[12]*m[1]*m[7] - m[12]*m[3]*m[5];
    inv[14] = -m[0]*m[5]*m[14] + m[0]*m[6]*m[13] + m[4]*m[1]*m[14]
             - m[4]*m[2]*m[13] - m[12]*m[1]*m[6] + m[12]*m[2]*m[5];
    inv[3]  = -m[1]*m[6]*m[11] + m[1]*m[7]*m[10] + m[5]*m[2]*m[11]
             - m[5]*m[3]*m[10] - m[9]*m[2]*m[7] + m[9]*m[3]*m[6];
    inv[7]  =  m[0]*m[6]*m[11] - m[0]*m[7]*m[10] - m[4]*m[2]*m[11]
             + m[4]*m[3]*m[10] + m[8]*m[2]*m[7] - m[8]*m[3]*m[6];
    inv[11] = -m[0]*m[5]*m[11] + m[0]*m[7]*m[9] + m[4]*m[1]*m[11]
             - m[4]*m[3]*m[9] - m[8]*m[1]*m[7] + m[8]*m[3]*m[5];
    inv[15] =  m[0]*m[5]*m[10] - m[0]*m[6]*m[9] - m[4]*m[1]*m[10]
             + m[4]*m[2]*m[9] + m[8]*m[1]*m[6] - m[8]*m[2]*m[5];
    float det = m[0]*inv[0] + m[1]*inv[4] + m[2]*inv[8] + m[3]*inv[12];
    float id = 1.0f / det;
    for (int i = 0; i < 16; i++) inv[i] *= id;
}

// ---------------------------------------------------------------------------
// Kernel 1: cost volume. Thread = (pixel, 4 depths). x fastest -> coalesced.
// Fast path (warp-uniform) skips zero-weight bilinear corners (wy==0 for this
// geometry); general path is the exact reference math.
// ---------------------------------------------------------------------------
__global__ void __launch_bounds__(128) cost_kernel(
    const float* __restrict__ feat,    // (V, C, H, W)
    const float* __restrict__ deps,    // (V, CD, H, W)
    const float* __restrict__ dvals,   // (D, H, W)
    const float* __restrict__ regw,    // (40)
    const float* __restrict__ proj)    // (V, 4, 4)
{
    __shared__ float sM[2][12];        // rot[0..8], tr[9..11] per src view
    __shared__ float sRW[C + CD];
    if (threadIdx.x == 0) {
        float inv[16];
        inv4x4(proj, inv);
        for (int v = 1; v < V; v++) {
            const float* P = proj + v * 16;
            for (int r = 0; r < 3; r++)
                for (int c2 = 0; c2 < 4; c2++) {
                    float s = P[r*4+0]*inv[0*4+c2] + P[r*4+1]*inv[1*4+c2]
                            + P[r*4+2]*inv[2*4+c2] + P[r*4+3]*inv[3*4+c2];
                    if (c2 < 3) sM[v-1][r*3 + c2] = s;
                    else        sM[v-1][9 + r]    = s;
                }
        }
    }
    if (threadIdx.x < C + CD) sRW[threadIdx.x] = regw[threadIdx.x];
    __syncthreads();

    const int pix = blockIdx.x * 128 + threadIdx.x;
    const int d0  = blockIdx.y * KD;
    const int y   = pix / W;
    const int x   = pix - y * W;
    const float xf = (float)x, yf = (float)y;

    int   lin[KD][2][4];
    float wt[KD][2][4];
    bool fast = true;

#pragma unroll
    for (int kd = 0; kd < KD; kd++) {
        const float dv = dvals[(d0 + kd) * HW + pix];
#pragma unroll
        for (int v = 0; v < 2; v++) {
            const float* M = sM[v];
            float r0 = M[0] * xf + M[1] * yf + M[2];
            float r1 = M[3] * xf + M[4] * yf + M[5];
            float r2 = M[6] * xf + M[7] * yf + M[8];
            float zx = r0 * dv + M[9];
            float zy = r1 * dv + M[10];
            float zz = r2 * dv + M[11];
            float iz = 1.0f / zz;
            float px = zx * iz;
            float py = zy * iz;
            float x0f = floorf(px), y0f = floorf(py);
            int   x0  = (int)x0f,   y0  = (int)y0f;
            float wx = px - x0f, wy = py - y0f;
            float vx0 = (x0 >= 0  && x0 < W)        ? 1.0f : 0.0f;
            float vx1 = (x0 + 1 >= 0 && x0 + 1 < W) ? 1.0f : 0.0f;
            float vy0 = (y0 >= 0  && y0 < H)        ? 1.0f : 0.0f;
            float vy1 = (y0 + 1 >= 0 && y0 + 1 < H) ? 1.0f : 0.0f;
            wt[kd][v][0] = (1.0f - wx) * (1.0f - wy) * vx0 * vy0;
            wt[kd][v][1] = wx * (1.0f - wy) * vx1 * vy0;
            wt[kd][v][2] = (1.0f - wx) * wy * vx0 * vy1;
            wt[kd][v][3] = wx * wy * vx1 * vy1;
            int cx0 = min(max(x0, 0), W - 1);
            int cx1 = min(max(x0 + 1, 0), W - 1);
            int cy0 = min(max(y0, 0), H - 1);
            int cy1 = min(max(y0 + 1, 0), H - 1);
            lin[kd][v][0] = cy0 * W + cx0;
            lin[kd][v][1] = cy0 * W + cx1;
            lin[kd][v][2] = cy1 * W + cx0;
            lin[kd][v][3] = cy1 * W + cx1;
            fast = fast && (wt[kd][v][2] == 0.0f) && (wt[kd][v][3] == 0.0f);
        }
    }
    // warp-uniform branch: all lanes must qualify, else everyone takes general
    fast = __all_sync(0xFFFFFFFFu, fast);

    constexpr float inv3 = 1.0f / 3.0f;
    float cost[KD];
#pragma unroll
    for (int kd = 0; kd < KD; kd++) cost[kd] = 0.0f;

    if (fast) {
        // Only y0-row corners carry weight: 2 loads per view per depth.
#pragma unroll 4
        for (int c = 0; c < C; c++) {
            const float rv = feat[c * HW + pix];
            const float* p1 = feat + (C + c) * HW;
            const float* p2 = feat + (2 * C + c) * HW;
            const float w = sRW[c];
#pragma unroll
            for (int kd = 0; kd < KD; kd++) {
                float s1 = p1[lin[kd][0][0]] * wt[kd][0][0]
                         + p1[lin[kd][0][1]] * wt[kd][0][1];
                float s2 = p2[lin[kd][1][0]] * wt[kd][1][0]
                         + p2[lin[kd][1][1]] * wt[kd][1][1];
                float s  = rv + s1 + s2;
                float sq = rv * rv + s1 * s1 + s2 * s2;
                float sm = s * inv3;
                cost[kd] += w * (sq * inv3 - sm * sm);
            }
        }
#pragma unroll 4
        for (int c = 0; c < CD; c++) {
            const float rv = deps[c * HW + pix];
            const float* p1 = deps + (CD + c) * HW;
            const float* p2 = deps + (2 * CD + c) * HW;
            const float w = sRW[C + c];
#pragma unroll
            for (int kd = 0; kd < KD; kd++) {
                float s1 = p1[lin[kd][0][0]] * wt[kd][0][0]
                         + p1[lin[kd][0][1]] * wt[kd][0][1];
                float s2 = p2[lin[kd][1][0]] * wt[kd][1][0]
                         + p2[lin[kd][1][1]] * wt[kd][1][1];
                float s  = rv + s1 + s2;
                float sq = rv * rv + s1 * s1 + s2 * s2;
                float sm = s * inv3;
                cost[kd] += w * (sq * inv3 - sm * sm);
            }
        }
    } else {
        // General 4-corner bilinear (exact reference math).
#pragma unroll 2
        for (int c = 0; c < C; c++) {
            const float rv = feat[c * HW + pix];
            const float* p1 = feat + (C + c) * HW;
            const float* p2 = feat + (2 * C + c) * HW;
            const float w = sRW[c];
#pragma unroll
            for (int kd = 0; kd < KD; kd++) {
                float s1 = p1[lin[kd][0][0]] * wt[kd][0][0]
                         + p1[lin[kd][0][1]] * wt[kd][0][1]
                         + p1[lin[kd][0][2]] * wt[kd][0][2]
                         + p1[lin[kd][0][3]] * wt[kd][0][3];
                float s2 = p2[lin[kd][1][0]] * wt[kd][1][0]
                         + p2[lin[kd][1][1]] * wt[kd][1][1]
                         + p2[lin[kd][1][2]] * wt[kd][1][2]
                         + p2[lin[kd][1][3]] * wt[kd][1][3];
                float s  = rv + s1 + s2;
                float sq = rv * rv + s1 * s1 + s2 * s2;
                float sm = s * inv3;
                cost[kd] += w * (sq * inv3 - sm * sm);
            }
        }
#pragma unroll 2
        for (int c = 0; c < CD; c++) {
            const float rv = deps[c * HW + pix];
            const float* p1 = deps + (CD + c) * HW;
            const float* p2 = deps + (2 * CD + c) * HW;
            const float w = sRW[C + c];
#pragma unroll
            for (int kd = 0; kd < KD; kd++) {
                float s1 = p1[lin[kd][0][0]] * wt[kd][0][0]
                         + p1[lin[kd][0][1]] * wt[kd][0][1]
                         + p1[lin[kd][0][2]] * wt[kd][0][2]
                         + p1[lin[kd][0][3]] * wt[kd][0][3];
                float s2 = p2[lin[kd][1][0]] * wt[kd][1][0]
                         + p2[lin[kd][1][1]] * wt[kd][1][1]
                         + p2[lin[kd][1][2]] * wt[kd][1][2]
                         + p2[lin[kd][1][3]] * wt[kd][1][3];
                float s  = rv + s1 + s2;
                float sq = rv * rv + s1 * s1 + s2 * s2;
                float sm = s * inv3;
                cost[kd] += w * (sq * inv3 - sm * sm);
            }
        }
    }

#pragma unroll
    for (int kd = 0; kd < KD; kd++)
        g_cost[(d0 + kd) * HW + pix] = cost[kd];
}

// ---------------------------------------------------------------------------
// Kernel 2: softmax over depth + depth / expected-variance moments.
// ---------------------------------------------------------------------------
__global__ void __launch_bounds__(128) softmax_kernel(
    const float* __restrict__ dvals,   // (D, H, W)
    float* __restrict__ out)           // [depth HW | exp_var HW | prob D*HW]
{
    const int pix = blockIdx.x * 128 + threadIdx.x;
    if (pix >= HW) return;

    float cv[D], dv[D];
#pragma unroll
    for (int d = 0; d < D; d++) {
        cv[d] = g_cost[d * HW + pix];
        dv[d] = dvals[d * HW + pix];
    }

    float m = cv[0];
#pragma unroll
    for (int d = 1; d < D; d++) m = fmaxf(m, cv[d]);

    float ssum = 0.0f;
#pragma unroll
    for (int d = 0; d < D; d++) { cv[d] = expf(cv[d] - m); ssum += cv[d]; }
    const float isum = 1.0f / ssum;

    float depthv = 0.0f;
#pragma unroll
    for (int d = 0; d < D; d++) {
        cv[d] *= isum;
        depthv += cv[d] * dv[d];
    }

    float var = 0.0f;
#pragma unroll
    for (int d = 0; d < D; d++) {
        float t = dv[d] - depthv;
        var += cv[d] * t * t;
        out[2 * HW + d * HW + pix] = cv[d];
    }

    out[pix]      = depthv;
    out[HW + pix] = LAMB * sqrtf(var);
}

} // namespace

extern "C" void kernel_launch(void* const* d_in, const int* in_sizes, int n_in,
                              void* d_out, int out_size) {
    const float* feat  = nullptr;
    const float* deps  = nullptr;
    const float* proj  = nullptr;
    const float* dvals = nullptr;
    const float* regw  = nullptr;
    for (int i = 0; i < n_in; i++) {
        switch (in_sizes[i]) {
            case V * C * HW:  feat  = (const float*)d_in[i]; break;
            case V * CD * HW: deps  = (const float*)d_in[i]; break;
            case V * 16:      proj  = (const float*)d_in[i]; break;
            case D * HW:      dvals = (const float*)d_in[i]; break;
            case C + CD:      regw  = (const float*)d_in[i]; break;
            default: break;
        }
    }
    float* out = (float*)d_out;

    dim3 grid(HW / 128, D / KD);
    cost_kernel<<<grid, 128>>>(feat, deps, dvals, regw, proj);
    softmax_kernel<<<HW / 128, 128>>>(dvals, out);
}

// round 4
// speedup vs baseline: 1.2840x; 1.2840x over previous
#include <cuda_runtime.h>
#include <math.h>

namespace {

constexpr int V  = 3;
constexpr int C  = 32;
constexpr int CD = 8;
constexpr int D  = 32;
constexpr int H  = 128;
constexpr int W  = 160;
constexpr int HW = H * W;
constexpr int KD = 4;            // depths per thread in cost kernel
constexpr float LAMB = 1.5f;
constexpr float EPSW = 1e-4f;    // wy snap threshold (noise is ~1e-5)

// Cost volume scratch (D, H, W)
__device__ float g_cost[D * HW];

// ---------------------------------------------------------------------------
// fp32 closed-form 4x4 inverse (adjugate).
// ---------------------------------------------------------------------------
__device__ __forceinline__ void inv4x4(const float* m, float* inv) {
    inv[0]  =  m[5]*m[10]*m[15] - m[5]*m[11]*m[14] - m[9]*m[6]*m[15]
             + m[9]*m[7]*m[14] + m[13]*m[6]*m[11] - m[13]*m[7]*m[10];
    inv[4]  = -m[4]*m[10]*m[15] + m[4]*m[11]*m[14] + m[8]*m[6]*m[15]
             - m[8]*m[7]*m[14] - m[12]*m[6]*m[11] + m[12]*m[7]*m[10];
    inv[8]  =  m[4]*m[9]*m[15] - m[4]*m[11]*m[13] - m[8]*m[5]*m[15]
             + m[8]*m[7]*m[13] + m[12]*m[5]*m[11] - m[12]*m[7]*m[9];
    inv[12] = -m[4]*m[9]*m[14] + m[4]*m[10]*m[13] + m[8]*m[5]*m[14]
             - m[8]*m[6]*m[13] - m[12]*m[5]*m[10] + m[12]*m[6]*m[9];
    inv[1]  = -m[1]*m[10]*m[15] + m[1]*m[11]*m[14] + m[9]*m[2]*m[15]
             - m[9]*m[3]*m[14] - m[13]*m[2]*m[11] + m[13]*m[3]*m[10];
    inv[5]  =  m[0]*m[10]*m[15] - m[0]*m[11]*m[14] - m[8]*m[2]*m[15]
             + m[8]*m[3]*m[14] + m[12]*m[2]*m[11] - m[12]*m[3]*m[10];
    inv[9]  = -m[0]*m[9]*m[15] + m[0]*m[11]*m[13] + m[8]*m[1]*m[15]
             - m[8]*m[3]*m[13] - m[12]*m[1]*m[11] + m[12]*m[3]*m[9];
    inv[13] =  m[0]*m[9]*m[14] - m[0]*m[10]*m[13] - m[8]*m[1]*m[14]
             + m[8]*m[2]*m[13] + m[12]*m[1]*m[10] - m[12]*m[2]*m[9];
    inv[2]  =  m[1]*m[6]*m[15] - m[1]*m[7]*m[14] - m[5]*m[2]*m[15]
             + m[5]*m[3]*m[14] + m[13]*m[2]*m[7] - m[13]*m[3]*m[6];
    inv[6]  = -m[0]*m[6]*m[15] + m[0]*m[7]*m[14] + m[4]*m[2]*m[15]
             - m[4]*m[3]*m[14] - m[12]*m[2]*m[7] + m[12]*m[3]*m[6];
    inv[10] =  m[0]*m[5]*m[15] - m[0]*m[7]*m[13] - m[4]*m[1]*m[15]
             + m[4]*m[3]*m[13] + m[12]*m[1]*m[7] - m[12]*m[3]*m[5];
    inv[14] = -m[0]*m[5]*m[14] + m[0]*m[6]*m[13] + m[4]*m[1]*m[14]
             - m[4]*m[2]*m[13] - m[12]*m[1]*m[6] + m[12]*m[2]*m[5];
    inv[3]  = -m[1]*m[6]*m[11] + m[1]*m[7]*m[10] + m[5]*m[2]*m[11]
             - m[5]*m[3]*m[10] - m[9]*m[2]*m[7] + m[9]*m[3]*m[6];
    inv[7]  =  m[0]*m[6]*m[11] - m[0]*m[7]*m[10] - m[4]*m[2]*m[11]
             + m[4]*m[3]*m[10] + m[8]*m[2]*m[7] - m[8]*m[3]*m[6];
    inv[11] = -m[0]*m[5]*m[11] + m[0]*m[7]*m[9] + m[4]*m[1]*m[11]
             - m[4]*m[3]*m[9] - m[8]*m[1]*m[7] + m[8]*m[3]*m[5];
    inv[15] =  m[0]*m[5]*m[10] - m[0]*m[6]*m[9] - m[4]*m[1]*m[10]
             + m[4]*m[2]*m[9] + m[8]*m[1]*m[6] - m[8]*m[2]*m[5];
    float det = m[0]*inv[0] + m[1]*inv[4] + m[2]*inv[8] + m[3]*inv[12];
    float id = 1.0f / det;
    for (int i = 0; i < 16; i++) inv[i] *= id;
}

// ---------------------------------------------------------------------------
// Kernel 1: cost volume. Thread = (pixel, KD depths). x fastest -> coalesced.
// Fast path (warp-uniform): wy within EPSW of 0 or 1 -> bilinear collapses to
// the dominant row (2 taps, keeping the (1-wy)/wy row factor; dropped terms
// are <= EPSW ~ 1e-4 relative). General 4-corner path is the exact fallback.
// ---------------------------------------------------------------------------
__global__ void __launch_bounds__(128) cost_kernel(
    const float* __restrict__ feat,    // (V, C, H, W)
    const float* __restrict__ deps,    // (V, CD, H, W)
    const float* __restrict__ dvals,   // (D, H, W)
    const float* __restrict__ regw,    // (40)
    const float* __restrict__ proj)    // (V, 4, 4)
{
    __shared__ float sM[2][12];        // rot[0..8], tr[9..11] per src view
    __shared__ float sRW[C + CD];
    if (threadIdx.x == 0) {
        float inv[16];
        inv4x4(proj, inv);
        for (int v = 1; v < V; v++) {
            const float* P = proj + v * 16;
            for (int r = 0; r < 3; r++)
                for (int c2 = 0; c2 < 4; c2++) {
                    float s = P[r*4+0]*inv[0*4+c2] + P[r*4+1]*inv[1*4+c2]
                            + P[r*4+2]*inv[2*4+c2] + P[r*4+3]*inv[3*4+c2];
                    if (c2 < 3) sM[v-1][r*3 + c2] = s;
                    else        sM[v-1][9 + r]    = s;
                }
        }
    }
    if (threadIdx.x < C + CD) sRW[threadIdx.x] = regw[threadIdx.x];
    __syncthreads();

    const int pix = blockIdx.x * 128 + threadIdx.x;
    const int d0  = blockIdx.y * KD;
    const int y   = pix / W;
    const int x   = pix - y * W;
    const float xf = (float)x, yf = (float)y;

    float pxs[KD][2], pys[KD][2];
    bool fast = true;

#pragma unroll
    for (int kd = 0; kd < KD; kd++) {
        const float dv = dvals[(d0 + kd) * HW + pix];
#pragma unroll
        for (int v = 0; v < 2; v++) {
            const float* M = sM[v];
            float r0 = M[0] * xf + M[1] * yf + M[2];
            float r1 = M[3] * xf + M[4] * yf + M[5];
            float r2 = M[6] * xf + M[7] * yf + M[8];
            float zx = r0 * dv + M[9];
            float zy = r1 * dv + M[10];
            float zz = r2 * dv + M[11];
            float iz = 1.0f / zz;
            float px = zx * iz;
            float py = zy * iz;
            pxs[kd][v] = px;
            pys[kd][v] = py;
            float wy = py - floorf(py);
            fast = fast && ((wy <= EPSW) || (wy >= 1.0f - EPSW));
        }
    }
    fast = __all_sync(0xFFFFFFFFu, fast);

    constexpr float inv3 = 1.0f / 3.0f;
    float cost[KD];
#pragma unroll
    for (int kd = 0; kd < KD; kd++) cost[kd] = 0.0f;

    if (fast) {
        // 2 taps per (depth, view): dominant row only.
        int   l0[KD][2];
        float w0[KD][2], w1[KD][2];
#pragma unroll
        for (int kd = 0; kd < KD; kd++) {
#pragma unroll
            for (int v = 0; v < 2; v++) {
                float px = pxs[kd][v], py = pys[kd][v];
                float x0f = floorf(px), y0f = floorf(py);
                int   x0  = (int)x0f,   y0  = (int)y0f;
                float wx = px - x0f,  wy = py - y0f;
                bool lowRow = (wy <= EPSW);
                int   yr   = lowRow ? y0 : (y0 + 1);
                float rowW = lowRow ? (1.0f - wy) : wy;
                float vy = (yr >= 0 && yr < H) ? 1.0f : 0.0f;
                float vx0 = (x0 >= 0 && x0 < W) ? 1.0f : 0.0f;
                float vx1 = (x0 + 1 >= 0 && x0 + 1 < W) ? 1.0f : 0.0f;
                rowW *= vy;
                w0[kd][v] = (1.0f - wx) * rowW * vx0;
                w1[kd][v] = wx * rowW * vx1;
                int cy  = min(max(yr, 0), H - 1);
                int cx0 = min(max(x0, 0), W - 1);
                l0[kd][v] = cy * W + cx0;
                // second tap is cx1; encode as separate index via clamp:
                // store delta in w1 path below using cx1
                int cx1 = min(max(x0 + 1, 0), W - 1);
                // pack: reuse l0 for tap0; tap1 index = l0 + (cx1 - cx0)
                l0[kd][v] = (cy * W + cx0) | ((cx1 - cx0) << 28);
            }
        }
#pragma unroll 4
        for (int c = 0; c < C + CD; c++) {
            const float* base = (c < C) ? (feat + c * HW) : (deps + (c - C) * HW);
            const int    vstr = (c < C) ? (C * HW) : (CD * HW);
            const float rv = base[pix];
            const float* p1 = base + vstr;
            const float* p2 = base + 2 * vstr;
            const float w = sRW[c];
#pragma unroll
            for (int kd = 0; kd < KD; kd++) {
                int i10 = l0[kd][0] & 0x0FFFFFFF;
                int i11 = i10 + (l0[kd][0] >> 28);
                int i20 = l0[kd][1] & 0x0FFFFFFF;
                int i21 = i20 + (l0[kd][1] >> 28);
                float s1 = p1[i10] * w0[kd][0] + p1[i11] * w1[kd][0];
                float s2 = p2[i20] * w0[kd][1] + p2[i21] * w1[kd][1];
                float s  = rv + s1 + s2;
                float sq = rv * rv + s1 * s1 + s2 * s2;
                float sm = s * inv3;
                cost[kd] += w * (sq * inv3 - sm * sm);
            }
        }
    } else {
        // General 4-corner bilinear (exact reference math).
        int   lin[KD][2][4];
        float wt[KD][2][4];
#pragma unroll
        for (int kd = 0; kd < KD; kd++) {
#pragma unroll
            for (int v = 0; v < 2; v++) {
                float px = pxs[kd][v], py = pys[kd][v];
                float x0f = floorf(px), y0f = floorf(py);
                int   x0  = (int)x0f,   y0  = (int)y0f;
                float wx = px - x0f, wy = py - y0f;
                float vx0 = (x0 >= 0  && x0 < W)        ? 1.0f : 0.0f;
                float vx1 = (x0 + 1 >= 0 && x0 + 1 < W) ? 1.0f : 0.0f;
                float vy0 = (y0 >= 0  && y0 < H)        ? 1.0f : 0.0f;
                float vy1 = (y0 + 1 >= 0 && y0 + 1 < H) ? 1.0f : 0.0f;
                wt[kd][v][0] = (1.0f - wx) * (1.0f - wy) * vx0 * vy0;
                wt[kd][v][1] = wx * (1.0f - wy) * vx1 * vy0;
                wt[kd][v][2] = (1.0f - wx) * wy * vx0 * vy1;
                wt[kd][v][3] = wx * wy * vx1 * vy1;
                int cx0 = min(max(x0, 0), W - 1);
                int cx1 = min(max(x0 + 1, 0), W - 1);
                int cy0 = min(max(y0, 0), H - 1);
                int cy1 = min(max(y0 + 1, 0), H - 1);
                lin[kd][v][0] = cy0 * W + cx0;
                lin[kd][v][1] = cy0 * W + cx1;
                lin[kd][v][2] = cy1 * W + cx0;
                lin[kd][v][3] = cy1 * W + cx1;
            }
        }
        for (int c = 0; c < C + CD; c++) {
            const float* base = (c < C) ? (feat + c * HW) : (deps + (c - C) * HW);
            const int    vstr = (c < C) ? (C * HW) : (CD * HW);
            const float rv = base[pix];
            const float* p1 = base + vstr;
            const float* p2 = base + 2 * vstr;
            const float w = sRW[c];
#pragma unroll
            for (int kd = 0; kd < KD; kd++) {
                float s1 = p1[lin[kd][0][0]] * wt[kd][0][0]
                         + p1[lin[kd][0][1]] * wt[kd][0][1]
                         + p1[lin[kd][0][2]] * wt[kd][0][2]
                         + p1[lin[kd][0][3]] * wt[kd][0][3];
                float s2 = p2[lin[kd][1][0]] * wt[kd][1][0]
                         + p2[lin[kd][1][1]] * wt[kd][1][1]
                         + p2[lin[kd][1][2]] * wt[kd][1][2]
                         + p2[lin[kd][1][3]] * wt[kd][1][3];
                float s  = rv + s1 + s2;
                float sq = rv * rv + s1 * s1 + s2 * s2;
                float sm = s * inv3;
                cost[kd] += w * (sq * inv3 - sm * sm);
            }
        }
    }

#pragma unroll
    for (int kd = 0; kd < KD; kd++)
        g_cost[(d0 + kd) * HW + pix] = cost[kd];
}

// ---------------------------------------------------------------------------
// Kernel 2: softmax over depth + depth / expected-variance moments.
// ---------------------------------------------------------------------------
__global__ void __launch_bounds__(128) softmax_kernel(
    const float* __restrict__ dvals,   // (D, H, W)
    float* __restrict__ out)           // [depth HW | exp_var HW | prob D*HW]
{
    const int pix = blockIdx.x * 128 + threadIdx.x;
    if (pix >= HW) return;

    float cv[D], dv[D];
#pragma unroll
    for (int d = 0; d < D; d++) {
        cv[d] = g_cost[d * HW + pix];
        dv[d] = dvals[d * HW + pix];
    }

    float m = cv[0];
#pragma unroll
    for (int d = 1; d < D; d++) m = fmaxf(m, cv[d]);

    float ssum = 0.0f;
#pragma unroll
    for (int d = 0; d < D; d++) { cv[d] = expf(cv[d] - m); ssum += cv[d]; }
    const float isum = 1.0f / ssum;

    float depthv = 0.0f;
#pragma unroll
    for (int d = 0; d < D; d++) {
        cv[d] *= isum;
        depthv += cv[d] * dv[d];
    }

    float var = 0.0f;
#pragma unroll
    for (int d = 0; d < D; d++) {
        float t = dv[d] - depthv;
        var += cv[d] * t * t;
        out[2 * HW + d * HW + pix] = cv[d];
    }

    out[pix]      = depthv;
    out[HW + pix] = LAMB * sqrtf(var);
}

} // namespace

extern "C" void kernel_launch(void* const* d_in, const int* in_sizes, int n_in,
                              void* d_out, int out_size) {
    const float* feat  = nullptr;
    const float* deps  = nullptr;
    const float* proj  = nullptr;
    const float* dvals = nullptr;
    const float* regw  = nullptr;
    for (int i = 0; i < n_in; i++) {
        switch (in_sizes[i]) {
            case V * C * HW:  feat  = (const float*)d_in[i]; break;
            case V * CD * HW: deps  = (const float*)d_in[i]; break;
            case V * 16:      proj  = (const float*)d_in[i]; break;
            case D * HW:      dvals = (const float*)d_in[i]; break;
            case C + CD:      regw  = (const float*)d_in[i]; break;
            default: break;
        }
    }
    float* out = (float*)d_out;

    dim3 grid(HW / 128, D / KD);
    cost_kernel<<<grid, 128>>>(feat, deps, dvals, regw, proj);
    softmax_kernel<<<HW / 128, 128>>>(dvals, out);
}

// round 5
// speedup vs baseline: 1.3945x; 1.0860x over previous
#include <cuda_runtime.h>
#include <math.h>
#include <limits.h>

namespace {

constexpr int V  = 3;
constexpr int C  = 32;
constexpr int CD = 8;
constexpr int D  = 32;
constexpr int H  = 128;
constexpr int W  = 160;
constexpr int HW = H * W;
constexpr int KD = 4;            // depths per thread (2 f32x2 pairs)
constexpr float LAMB = 1.5f;
constexpr float EPSW = 1e-4f;    // wy snap threshold (fp32 noise ~1e-5)

__device__ float g_cost[D * HW];

typedef unsigned long long ull;
__device__ __forceinline__ ull pk2(float lo, float hi) {
    ull r; asm("mov.b64 %0,{%1,%2};" : "=l"(r) : "f"(lo), "f"(hi)); return r;
}
__device__ __forceinline__ void upk2(ull v, float& lo, float& hi) {
    asm("mov.b64 {%0,%1},%2;" : "=f"(lo), "=f"(hi) : "l"(v));
}
__device__ __forceinline__ ull fma2_(ull a, ull b, ull c) {
    ull d; asm("fma.rn.f32x2 %0,%1,%2,%3;" : "=l"(d) : "l"(a), "l"(b), "l"(c)); return d;
}
__device__ __forceinline__ ull mul2_(ull a, ull b) {
    ull d; asm("mul.rn.f32x2 %0,%1,%2;" : "=l"(d) : "l"(a), "l"(b)); return d;
}
__device__ __forceinline__ ull add2_(ull a, ull b) {
    ull d; asm("add.rn.f32x2 %0,%1,%2;" : "=l"(d) : "l"(a), "l"(b)); return d;
}

__device__ __forceinline__ void inv4x4(const float* m, float* inv) {
    inv[0]  =  m[5]*m[10]*m[15] - m[5]*m[11]*m[14] - m[9]*m[6]*m[15]
             + m[9]*m[7]*m[14] + m[13]*m[6]*m[11] - m[13]*m[7]*m[10];
    inv[4]  = -m[4]*m[10]*m[15] + m[4]*m[11]*m[14] + m[8]*m[6]*m[15]
             - m[8]*m[7]*m[14] - m[12]*m[6]*m[11] + m[12]*m[7]*m[10];
    inv[8]  =  m[4]*m[9]*m[15] - m[4]*m[11]*m[13] - m[8]*m[5]*m[15]
             + m[8]*m[7]*m[13] + m[12]*m[5]*m[11] - m[12]*m[7]*m[9];
    inv[12] = -m[4]*m[9]*m[14] + m[4]*m[10]*m[13] + m[8]*m[5]*m[14]
             - m[8]*m[6]*m[13] - m[12]*m[5]*m[10] + m[12]*m[6]*m[9];
    inv[1]  = -m[1]*m[10]*m[15] + m[1]*m[11]*m[14] + m[9]*m[2]*m[15]
             - m[9]*m[3]*m[14] - m[13]*m[2]*m[11] + m[13]*m[3]*m[10];
    inv[5]  =  m[0]*m[10]*m[15] - m[0]*m[11]*m[14] - m[8]*m[2]*m[15]
             + m[8]*m[3]*m[14] + m[12]*m[2]*m[11] - m[12]*m[3]*m[10];
    inv[9]  = -m[0]*m[9]*m[15] + m[0]*m[11]*m[13] + m[8]*m[1]*m[15]
             - m[8]*m[3]*m[13] - m[12]*m[1]*m[11] + m[12]*m[3]*m[9];
    inv[13] =  m[0]*m[9]*m[14] - m[0]*m[10]*m[13] - m[8]*m[1]*m[14]
             + m[8]*m[2]*m[13] + m[12]*m[1]*m[10] - m[12]*m[2]*m[9];
    inv[2]  =  m[1]*m[6]*m[15] - m[1]*m[7]*m[14] - m[5]*m[2]*m[15]
             + m[5]*m[3]*m[14] + m[13]*m[2]*m[7] - m[13]*m[3]*m[6];
    inv[6]  = -m[0]*m[6]*m[15] + m[0]*m[7]*m[14] + m[4]*m[2]*m[15]
             - m[4]*m[3]*m[14] - m[12]*m[2]*m[7] + m[12]*m[3]*m[6];
    inv[10] =  m[0]*m[5]*m[15] - m[0]*m[7]*m[13] - m[4]*m[1]*m[15]
             + m[4]*m[3]*m[13] + m[12]*m[1]*m[7] - m[12]*m[3]*m[5];
    inv[14] = -m[0]*m[5]*m[14] + m[0]*m[6]*m[13] + m[4]*m[1]*m[14]
             - m[4]*m[2]*m[13] - m[12]*m[1]*m[6] + m[12]*m[2]*m[5];
    inv[3]  = -m[1]*m[6]*m[11] + m[1]*m[7]*m[10] + m[5]*m[2]*m[11]
             - m[5]*m[3]*m[10] - m[9]*m[2]*m[7] + m[9]*m[3]*m[6];
    inv[7]  =  m[0]*m[6]*m[11] - m[0]*m[7]*m[10] - m[4]*m[2]*m[11]
             + m[4]*m[3]*m[10] + m[8]*m[2]*m[7] - m[8]*m[3]*m[6];
    inv[11] = -m[0]*m[5]*m[11] + m[0]*m[7]*m[9] + m[4]*m[1]*m[11]
             - m[4]*m[3]*m[9] - m[8]*m[1]*m[7] + m[8]*m[3]*m[5];
    inv[15] =  m[0]*m[5]*m[10] - m[0]*m[6]*m[9] - m[4]*m[1]*m[10]
             + m[4]*m[2]*m[9] + m[8]*m[1]*m[6] - m[8]*m[2]*m[5];
    float det = m[0]*inv[0] + m[1]*inv[4] + m[2]*inv[8] + m[3]*inv[12];
    float id = 1.0f / det;
    for (int i = 0; i < 16; i++) inv[i] *= id;
}

// ---------------------------------------------------------------------------
// Cost volume kernel. Block = 128 threads (x fastest); warps never straddle
// image rows (W = 5*32). Fast path: taps collapse to one row (wy ~ 0/1) ->
// stage the warp's row segment in SMEM as aligned (tap, tap+1) float2 pairs,
// then each tap pair is one LDS.64. Variance math packed as f32x2 over depth
// pairs. Fallback: exact 4-corner bilinear from GMEM.
// ---------------------------------------------------------------------------
__global__ void __launch_bounds__(128) cost_kernel(
    const float* __restrict__ feat,    // (V, C, H, W)
    const float* __restrict__ deps,    // (V, CD, H, W)
    const float* __restrict__ dvals,   // (D, H, W)
    const float* __restrict__ regw,    // (40)
    const float* __restrict__ proj)    // (V, 4, 4)
{
    __shared__ float  sM[2][12];
    __shared__ float  sRW[C + CD];     // original weights (fallback)
    __shared__ float  sRW2[C + CD];    // * 2/9 (fast path)
    __shared__ float2 sPair[2][4][2][64];  // [buf][warp][view][pair]

    if (threadIdx.x == 0) {
        float inv[16];
        inv4x4(proj, inv);
        for (int v = 1; v < V; v++) {
            const float* P = proj + v * 16;
            for (int r = 0; r < 3; r++)
                for (int c2 = 0; c2 < 4; c2++) {
                    float s = P[r*4+0]*inv[0*4+c2] + P[r*4+1]*inv[1*4+c2]
                            + P[r*4+2]*inv[2*4+c2] + P[r*4+3]*inv[3*4+c2];
                    if (c2 < 3) sM[v-1][r*3 + c2] = s;
                    else        sM[v-1][9 + r]    = s;
                }
        }
    }
    if (threadIdx.x < C + CD) {
        float wv = regw[threadIdx.x];
        sRW[threadIdx.x]  = wv;
        sRW2[threadIdx.x] = wv * (2.0f / 9.0f);
    }
    __syncthreads();

    const int tid  = threadIdx.x;
    const int wrp  = tid >> 5;
    const int lane = tid & 31;
    const int pix  = blockIdx.x * 128 + tid;
    const int d0   = blockIdx.y * KD;
    const int y    = pix / W;
    const int x    = pix - y * W;
    const int yW   = y * W;
    const float xf = (float)x, yf = (float)y;

    float pxs[KD][2], pys[KD][2];
    float wa[KD][2],  wb[KD][2];
    int   q[KD][2];
    int   mn0 = INT_MAX, mn1 = INT_MAX;
    bool  ok = true;

#pragma unroll
    for (int kd = 0; kd < KD; kd++) {
        const float dv = dvals[(d0 + kd) * HW + pix];
#pragma unroll
        for (int v = 0; v < 2; v++) {
            const float* M = sM[v];
            float r0 = M[0] * xf + M[1] * yf + M[2];
            float r1 = M[3] * xf + M[4] * yf + M[5];
            float r2 = M[6] * xf + M[7] * yf + M[8];
            float zx = r0 * dv + M[9];
            float zy = r1 * dv + M[10];
            float zz = r2 * dv + M[11];
            float iz = 1.0f / zz;
            float px = zx * iz;
            float py = zy * iz;
            pxs[kd][v] = px;
            pys[kd][v] = py;

            float x0f = floorf(px), y0f = floorf(py);
            int   x0  = (int)x0f;
            int   y0  = (int)y0f;
            float wx = px - x0f, wy = py - y0f;
            bool  low = (wy <= EPSW);
            int   yr  = low ? y0 : (y0 + 1);
            float rowW = low ? (1.0f - wy) : wy;
            ok = ok && ((wy <= EPSW) || (wy >= 1.0f - EPSW)) && (yr == y);
            float vx0 = (x0 >= 0 && x0 < W) ? 1.0f : 0.0f;
            float vx1 = (x0 + 1 >= 0 && x0 + 1 < W) ? 1.0f : 0.0f;
            wa[kd][v] = (1.0f - wx) * rowW * vx0;
            wb[kd][v] = wx * rowW * vx1;
            q[kd][v]  = x0;
            if (v == 0) mn0 = min(mn0, x0); else mn1 = min(mn1, x0);
        }
    }

    const unsigned FULL = 0xFFFFFFFFu;
    const int B0 = __shfl_sync(FULL, mn0, 0) - 1;
    const int B1 = __shfl_sync(FULL, mn1, 0) - 1;

    int ls[KD][2];
#pragma unroll
    for (int kd = 0; kd < KD; kd++) {
        ls[kd][0] = q[kd][0] - B0;
        ls[kd][1] = q[kd][1] - B1;
        ok = ok && ((unsigned)ls[kd][0] <= 62u) && ((unsigned)ls[kd][1] <= 62u);
    }
    const bool fast = __all_sync(FULL, ok);

    float costv[KD];

    if (fast) {
        // Staging fetch offsets (clamped into the row; zero-weight taps may
        // read clamped duplicates -- harmless).
        const int o00 = yW + min(max(B0 + lane,      0), W - 1);
        const int o01 = yW + min(max(B0 + 32 + lane, 0), W - 1);
        const int o10 = yW + min(max(B1 + lane,      0), W - 1);
        const int o11 = yW + min(max(B1 + 32 + lane, 0), W - 1);

        // Packed weights per (view, depth-pair)
        ull WA[2][2], WB[2][2];
#pragma unroll
        for (int v = 0; v < 2; v++)
#pragma unroll
            for (int g = 0; g < 2; g++) {
                WA[v][g] = pk2(wa[2*g][v], wa[2*g+1][v]);
                WB[v][g] = pk2(wb[2*g][v], wb[2*g+1][v]);
            }

        ull COST[2] = {0ull, 0ull};   // bit pattern 0 == (0.f, 0.f)

        for (int c = 0; c < C + CD; c++) {
            const float* refp;
            const float* p1;
            const float* p2;
            if (c < C) {
                refp = feat + c * HW;
                p1   = feat + (C + c) * HW;
                p2   = feat + (2 * C + c) * HW;
            } else {
                refp = deps + (c - C) * HW;
                p1   = deps + (CD + (c - C)) * HW;
                p2   = deps + (2 * CD + (c - C)) * HW;
            }

            // Stage both views' segments as (s[i], s[i+1]) float2 pairs.
            float a0 = __ldg(p1 + o00), a1 = __ldg(p1 + o01);
            float b0 = __ldg(p2 + o10), b1 = __ldg(p2 + o11);

            float ay = __shfl_sync(FULL, a0, (lane + 1) & 31);
            float ax = __shfl_sync(FULL, a1, 0);
            if (lane == 31) ay = ax;
            float az = __shfl_sync(FULL, a1, (lane + 1) & 31);  // lane31 junk (pair 63 unused)
            float by = __shfl_sync(FULL, b0, (lane + 1) & 31);
            float bx = __shfl_sync(FULL, b1, 0);
            if (lane == 31) by = bx;
            float bz = __shfl_sync(FULL, b1, (lane + 1) & 31);

            const int buf = c & 1;
            sPair[buf][wrp][0][lane]      = make_float2(a0, ay);
            sPair[buf][wrp][0][32 + lane] = make_float2(a1, az);
            sPair[buf][wrp][1][lane]      = make_float2(b0, by);
            sPair[buf][wrp][1][32 + lane] = make_float2(b1, bz);
            __syncwarp();

            const float rv = __ldg(refp + pix);
            const ull RV  = pk2(rv, rv);
            const ull RV2 = mul2_(RV, RV);
            const float w2 = sRW2[c];
            const ull WC  = pk2(w2, w2);
            const ull WCn = pk2(-w2, -w2);
            const float2* sp0 = sPair[buf][wrp][0];
            const float2* sp1 = sPair[buf][wrp][1];

#pragma unroll
            for (int g = 0; g < 2; g++) {
                float2 t00 = sp0[ls[2*g][0]];
                float2 t01 = sp0[ls[2*g+1][0]];
                float2 t10 = sp1[ls[2*g][1]];
                float2 t11 = sp1[ls[2*g+1][1]];
                ull S1 = fma2_(pk2(t00.y, t01.y), WB[0][g],
                               mul2_(pk2(t00.x, t01.x), WA[0][g]));
                ull S2 = fma2_(pk2(t10.y, t11.y), WB[1][g],
                               mul2_(pk2(t10.x, t11.x), WA[1][g]));
                ull CR = fma2_(RV, add2_(S1, S2), mul2_(S1, S2));
                ull SF = fma2_(S2, S2, fma2_(S1, S1, RV2));
                COST[g] = fma2_(SF, WC,  COST[g]);
                COST[g] = fma2_(CR, WCn, COST[g]);
            }
        }
        upk2(COST[0], costv[0], costv[1]);
        upk2(COST[1], costv[2], costv[3]);
    } else {
        // Exact 4-corner bilinear fallback (reference math).
        int   lin[KD][2][4];
        float wt[KD][2][4];
#pragma unroll
        for (int kd = 0; kd < KD; kd++) {
#pragma unroll
            for (int v = 0; v < 2; v++) {
                float px = pxs[kd][v], py = pys[kd][v];
                float x0f = floorf(px), y0f = floorf(py);
                int   x0  = (int)x0f,   y0  = (int)y0f;
                float wx = px - x0f, wy = py - y0f;
                float vx0 = (x0 >= 0  && x0 < W)        ? 1.0f : 0.0f;
                float vx1 = (x0 + 1 >= 0 && x0 + 1 < W) ? 1.0f : 0.0f;
                float vy0 = (y0 >= 0  && y0 < H)        ? 1.0f : 0.0f;
                float vy1 = (y0 + 1 >= 0 && y0 + 1 < H) ? 1.0f : 0.0f;
                wt[kd][v][0] = (1.0f - wx) * (1.0f - wy) * vx0 * vy0;
                wt[kd][v][1] = wx * (1.0f - wy) * vx1 * vy0;
                wt[kd][v][2] = (1.0f - wx) * wy * vx0 * vy1;
                wt[kd][v][3] = wx * wy * vx1 * vy1;
                int cx0 = min(max(x0, 0), W - 1);
                int cx1 = min(max(x0 + 1, 0), W - 1);
                int cy0 = min(max(y0, 0), H - 1);
                int cy1 = min(max(y0 + 1, 0), H - 1);
                lin[kd][v][0] = cy0 * W + cx0;
                lin[kd][v][1] = cy0 * W + cx1;
                lin[kd][v][2] = cy1 * W + cx0;
                lin[kd][v][3] = cy1 * W + cx1;
            }
        }
        constexpr float inv3 = 1.0f / 3.0f;
#pragma unroll
        for (int kd = 0; kd < KD; kd++) costv[kd] = 0.0f;
        for (int c = 0; c < C + CD; c++) {
            const float* base = (c < C) ? (feat + c * HW) : (deps + (c - C) * HW);
            const int    vstr = (c < C) ? (C * HW) : (CD * HW);
            const float rv = base[pix];
            const float* p1 = base + vstr;
            const float* p2 = base + 2 * vstr;
            const float wv = sRW[c];
#pragma unroll
            for (int kd = 0; kd < KD; kd++) {
                float s1 = p1[lin[kd][0][0]] * wt[kd][0][0]
                         + p1[lin[kd][0][1]] * wt[kd][0][1]
                         + p1[lin[kd][0][2]] * wt[kd][0][2]
                         + p1[lin[kd][0][3]] * wt[kd][0][3];
                float s2 = p2[lin[kd][1][0]] * wt[kd][1][0]
                         + p2[lin[kd][1][1]] * wt[kd][1][1]
                         + p2[lin[kd][1][2]] * wt[kd][1][2]
                         + p2[lin[kd][1][3]] * wt[kd][1][3];
                float s  = rv + s1 + s2;
                float sq = rv * rv + s1 * s1 + s2 * s2;
                float sm = s * inv3;
                costv[kd] += wv * (sq * inv3 - sm * sm);
            }
        }
    }

#pragma unroll
    for (int kd = 0; kd < KD; kd++)
        g_cost[(d0 + kd) * HW + pix] = costv[kd];
}

// ---------------------------------------------------------------------------
// Softmax over depth + depth / expected-variance moments.
// ---------------------------------------------------------------------------
__global__ void __launch_bounds__(128) softmax_kernel(
    const float* __restrict__ dvals,   // (D, H, W)
    float* __restrict__ out)           // [depth HW | exp_var HW | prob D*HW]
{
    const int pix = blockIdx.x * 128 + threadIdx.x;
    if (pix >= HW) return;

    float cv[D], dv[D];
#pragma unroll
    for (int d = 0; d < D; d++) {
        cv[d] = g_cost[d * HW + pix];
        dv[d] = dvals[d * HW + pix];
    }

    float m = cv[0];
#pragma unroll
    for (int d = 1; d < D; d++) m = fmaxf(m, cv[d]);

    float ssum = 0.0f;
#pragma unroll
    for (int d = 0; d < D; d++) { cv[d] = expf(cv[d] - m); ssum += cv[d]; }
    const float isum = 1.0f / ssum;

    float depthv = 0.0f;
#pragma unroll
    for (int d = 0; d < D; d++) {
        cv[d] *= isum;
        depthv += cv[d] * dv[d];
    }

    float var = 0.0f;
#pragma unroll
    for (int d = 0; d < D; d++) {
        float t = dv[d] - depthv;
        var += cv[d] * t * t;
        out[2 * HW + d * HW + pix] = cv[d];
    }

    out[pix]      = depthv;
    out[HW + pix] = LAMB * sqrtf(var);
}

} // namespace

extern "C" void kernel_launch(void* const* d_in, const int* in_sizes, int n_in,
                              void* d_out, int out_size) {
    const float* feat  = nullptr;
    const float* deps  = nullptr;
    const float* proj  = nullptr;
    const float* dvals = nullptr;
    const float* regw  = nullptr;
    for (int i = 0; i < n_in; i++) {
        switch (in_sizes[i]) {
            case V * C * HW:  feat  = (const float*)d_in[i]; break;
            case V * CD * HW: deps  = (const float*)d_in[i]; break;
            case V * 16:      proj  = (const float*)d_in[i]; break;
            case D * HW:      dvals = (const float*)d_in[i]; break;
            case C + CD:      regw  = (const float*)d_in[i]; break;
            default: break;
        }
    }
    float* out = (float*)d_out;

    dim3 grid(HW / 128, D / KD);
    cost_kernel<<<grid, 128>>>(feat, deps, dvals, regw, proj);
    softmax_kernel<<<HW / 128, 128>>>(dvals, out);
}